// round 1
// baseline (speedup 1.0000x reference)
#include <cuda_runtime.h>
#include <cuda_bf16.h>
#include <math.h>

#define D   512
#define MAXN 8192
#define BM  128
#define BN  128
#define BK  32
#define LDSW 40            // smem row stride in bf16 elems (pad 32->40: conflict-free ldmatrix)
#define NBLK (MAXN / BN)   // 64 column-blocks

// scratch (no cudaMalloc allowed)
__device__ __nv_bfloat16 g_fb[MAXN * D];
__device__ float  g_ptot[(size_t)MAXN * NBLK];
__device__ float  g_ppos[(size_t)MAXN * NBLK];
__device__ double g_bsum[64];

__device__ __forceinline__ unsigned smem_u32(const void* p) {
    return (unsigned)__cvta_generic_to_shared(p);
}

#define CPA(dst, src) asm volatile("cp.async.cg.shared.global [%0], [%1], 16;\n" :: "r"(dst), "l"(src))
#define CPCOMMIT()    asm volatile("cp.async.commit_group;\n")

#define LDSM4(r0, r1, r2, r3, addr) \
    asm volatile("ldmatrix.sync.aligned.m8n8.x4.shared.b16 {%0,%1,%2,%3}, [%4];\n" \
                 : "=r"(r0), "=r"(r1), "=r"(r2), "=r"(r3) : "r"(addr))

#define MMA16816(d0, d1, d2, d3, a0, a1, a2, a3, b0, b1) \
    asm volatile("mma.sync.aligned.m16n8k16.row.col.f32.bf16.bf16.f32 " \
                 "{%0,%1,%2,%3}, {%4,%5,%6,%7}, {%8,%9}, {%0,%1,%2,%3};\n" \
                 : "+f"(d0), "+f"(d1), "+f"(d2), "+f"(d3) \
                 : "r"(a0), "r"(a1), "r"(a2), "r"(a3), "r"(b0), "r"(b1))

// ---------------------------------------------------------------------------
// Kernel 1: L2-normalize rows -> bf16 scratch
// ---------------------------------------------------------------------------
__global__ void k_norm(const float* __restrict__ f, int N) {
    int row = blockIdx.x;
    __shared__ float red[8];
    const float* fr = f + (size_t)row * D;
    float ss = 0.f;
    for (int c = threadIdx.x; c < D; c += 256) { float v = fr[c]; ss += v * v; }
    for (int o = 16; o; o >>= 1) ss += __shfl_xor_sync(~0u, ss, o);
    if ((threadIdx.x & 31) == 0) red[threadIdx.x >> 5] = ss;
    __syncthreads();
    if (threadIdx.x < 32) {
        float v = (threadIdx.x < 8) ? red[threadIdx.x] : 0.f;
        for (int o = 4; o; o >>= 1) v += __shfl_xor_sync(~0u, v, o);
        if (threadIdx.x == 0) red[0] = v;
    }
    __syncthreads();
    float inv = 1.0f / fmaxf(sqrtf(red[0]), 1e-12f);
    __nv_bfloat16* out = g_fb + (size_t)row * D;
    for (int c = threadIdx.x; c < D; c += 256)
        out[c] = __float2bfloat16(fr[c] * inv);
}

// ---------------------------------------------------------------------------
// Kernel 2: fused S = f f^T tile GEMM + exp + masked row reductions.
// Deterministic: per-warp smem slices, per-(row, colBlock) global partials.
// ---------------------------------------------------------------------------
__global__ __launch_bounds__(256, 2)
void k_gemm(const int* __restrict__ labels, int N) {
    __shared__ __nv_bfloat16 sA[2][BM * LDSW];
    __shared__ __nv_bfloat16 sB[2][BN * LDSW];
    __shared__ int   lA[BM], lB[BN];
    __shared__ float wtot[8][64], wpos[8][64];

    const int tid  = threadIdx.x;
    const int lane = tid & 31;
    const int wid  = tid >> 5;
    const int wm   = wid >> 2;   // 0..1  (64 rows each)
    const int wn   = wid & 3;    // 0..3  (32 cols each)
    const int bi0  = blockIdx.y * BM;
    const int bj0  = blockIdx.x * BN;

    if (tid < BM)       lA[tid]        = labels[bi0 + tid];
    else                lB[tid - BM]   = labels[bj0 + (tid - BM)];

    // global->shared copy geometry: each thread owns one row, two 16B chunks
    const int lrow  = tid >> 1;
    const int cbase = (tid & 1) * 16;   // element offset

#define LOAD_TILE(st, kt) do {                                                    \
        const __nv_bfloat16* ga = g_fb + (size_t)(bi0 + lrow) * D + (kt) * BK + cbase; \
        const __nv_bfloat16* gb = g_fb + (size_t)(bj0 + lrow) * D + (kt) * BK + cbase; \
        unsigned da = smem_u32(&sA[st][lrow * LDSW + cbase]);                     \
        unsigned db = smem_u32(&sB[st][lrow * LDSW + cbase]);                     \
        CPA(da, ga); CPA(da + 16, ga + 8);                                        \
        CPA(db, gb); CPA(db + 16, gb + 8);                                        \
        CPCOMMIT();                                                               \
    } while (0)

    float acc[4][4][4];
#pragma unroll
    for (int mt = 0; mt < 4; ++mt)
#pragma unroll
        for (int nt = 0; nt < 4; ++nt)
#pragma unroll
            for (int k = 0; k < 4; ++k) acc[mt][nt][k] = 0.f;

    const int KT = D / BK;  // 16
    LOAD_TILE(0, 0);

    for (int kt = 0; kt < KT; ++kt) {
        const int st = kt & 1;
        if (kt + 1 < KT) {
            LOAD_TILE((kt + 1) & 1, kt + 1);
            asm volatile("cp.async.wait_group 1;\n");
        } else {
            asm volatile("cp.async.wait_group 0;\n");
        }
        __syncthreads();

#pragma unroll
        for (int kc = 0; kc < 2; ++kc) {          // two k16 chunks per BK=32
            unsigned a[4][4], b[4][2];
#pragma unroll
            for (int mt = 0; mt < 4; ++mt) {
                int arow = wm * 64 + mt * 16 + (lane & 15);
                int acol = kc * 16 + ((lane >> 4) << 3);
                LDSM4(a[mt][0], a[mt][1], a[mt][2], a[mt][3],
                      smem_u32(&sA[st][arow * LDSW + acol]));
            }
#pragma unroll
            for (int p = 0; p < 2; ++p) {
                int brow = wn * 32 + p * 16 + ((lane >> 4) << 3) + (lane & 7);
                int bcol = kc * 16 + (((lane >> 3) & 1) << 3);
                LDSM4(b[2 * p][0], b[2 * p][1], b[2 * p + 1][0], b[2 * p + 1][1],
                      smem_u32(&sB[st][brow * LDSW + bcol]));
            }
#pragma unroll
            for (int mt = 0; mt < 4; ++mt)
#pragma unroll
                for (int nt = 0; nt < 4; ++nt)
                    MMA16816(acc[mt][nt][0], acc[mt][nt][1], acc[mt][nt][2], acc[mt][nt][3],
                             a[mt][0], a[mt][1], a[mt][2], a[mt][3],
                             b[nt][0], b[nt][1]);
        }
        __syncthreads();
    }

    // epilogue: e = exp(s/T) = exp2(s * log2e/0.07); masked row sums
    const float SC = 20.60992915555662f;
#pragma unroll
    for (int mt = 0; mt < 4; ++mt) {
#pragma unroll
        for (int r = 0; r < 2; ++r) {
            const int li = wm * 64 + mt * 16 + (lane >> 2) + r * 8;
            const int gi = bi0 + li;
            const int la = lA[li];
            float t = 0.f, pq = 0.f;
#pragma unroll
            for (int nt = 0; nt < 4; ++nt) {
#pragma unroll
                for (int c = 0; c < 2; ++c) {
                    const int lj = wn * 32 + nt * 8 + (lane & 3) * 2 + c;
                    const int gj = bj0 + lj;
                    float e = exp2f(acc[mt][nt][r * 2 + c] * SC);
                    if (gi != gj) {
                        t += e;
                        if (la == lB[lj]) pq += e;
                    }
                }
            }
            // reduce across the 4 lanes sharing this row (lane&3 group)
            t  += __shfl_xor_sync(~0u, t, 1);  t  += __shfl_xor_sync(~0u, t, 2);
            pq += __shfl_xor_sync(~0u, pq, 1); pq += __shfl_xor_sync(~0u, pq, 2);
            if ((lane & 3) == 0) {
                int wr = mt * 16 + r * 8 + (lane >> 2);  // row within warp's 64
                wtot[wid][wr] = t;
                wpos[wid][wr] = pq;
            }
        }
    }
    __syncthreads();

    // deterministic combine of 4 warp_n slices -> per-block partial
    if (tid < BM) {
        const int wmm = tid >> 6;
        const int wr  = tid & 63;
        float t = 0.f, p = 0.f;
#pragma unroll
        for (int w = 0; w < 4; ++w) {
            t += wtot[wmm * 4 + w][wr];
            p += wpos[wmm * 4 + w][wr];
        }
        const int gi = bi0 + wmm * 64 + wr;
        g_ptot[(size_t)gi * NBLK + blockIdx.x] = t;
        g_ppos[(size_t)gi * NBLK + blockIdx.x] = p;
    }
#undef LOAD_TILE
}

// ---------------------------------------------------------------------------
// Kernel 3: per-row combine + log, block partial sums (double)
// ---------------------------------------------------------------------------
__global__ void k_row(int N) {
    const int row = blockIdx.x * 128 + threadIdx.x;
    float t = 0.f, p = 0.f;
    const float* pt = g_ptot + (size_t)row * NBLK;
    const float* pp = g_ppos + (size_t)row * NBLK;
#pragma unroll 8
    for (int k = 0; k < NBLK; ++k) { t += pt[k]; p += pp[k]; }
    float ratio = (p + 1e-7f * t) / t;
    __shared__ double sred[128];
    sred[threadIdx.x] = (double)logf(ratio);
    __syncthreads();
    for (int s = 64; s; s >>= 1) {
        if (threadIdx.x < s) sred[threadIdx.x] += sred[threadIdx.x + s];
        __syncthreads();
    }
    if (threadIdx.x == 0) g_bsum[blockIdx.x] = sred[0];
}

// ---------------------------------------------------------------------------
// Kernel 4: final reduction, mean, negate, finiteness guard
// ---------------------------------------------------------------------------
__global__ void k_final(float* __restrict__ out, int N) {
    __shared__ double sred[64];
    sred[threadIdx.x] = g_bsum[threadIdx.x];
    __syncthreads();
    for (int s = 32; s; s >>= 1) {
        if (threadIdx.x < s) sred[threadIdx.x] += sred[threadIdx.x + s];
        __syncthreads();
    }
    if (threadIdx.x == 0) {
        float L = (float)(-sred[0] / (double)N);
        if (!isfinite(L)) L = 0.f;
        out[0] = L;
    }
}

extern "C" void kernel_launch(void* const* d_in, const int* in_sizes, int n_in,
                              void* d_out, int out_size) {
    const float* f  = (const float*)d_in[0];
    const int*   lb = (const int*)d_in[1];   // jax int64 request downcasts to int32 (x64 off)
    int N = in_sizes[1];                     // 8192

    k_norm<<<N, 256>>>(f, N);
    dim3 grid(N / BN, N / BM);
    k_gemm<<<grid, 256>>>(lb, N);
    k_row<<<N / 128, 128>>>(N);
    k_final<<<1, 64>>>((float*)d_out, N);
}

// round 2
// speedup vs baseline: 1.7083x; 1.7083x over previous
#include <cuda_runtime.h>
#include <cuda_bf16.h>
#include <math.h>

#define D   512
#define MAXN 8192
#define BM  128
#define BN  128
#define BK  32
#define LDSW 40            // smem row stride in bf16 elems (pad 32->40: conflict-free ldmatrix)
#define NBLK (MAXN / BN)   // 64 column-blocks

// scratch (no cudaMalloc allowed)
__device__ __nv_bfloat16 g_fb[MAXN * D];
__device__ float  g_ptot[(size_t)MAXN * NBLK];
__device__ float  g_ppos[(size_t)MAXN * NBLK];
__device__ double g_bsum[64];

__device__ __forceinline__ unsigned smem_u32(const void* p) {
    return (unsigned)__cvta_generic_to_shared(p);
}

#define CPA(dst, src) asm volatile("cp.async.cg.shared.global [%0], [%1], 16;\n" :: "r"(dst), "l"(src))
#define CPCOMMIT()    asm volatile("cp.async.commit_group;\n")

#define LDSM4(r0, r1, r2, r3, addr) \
    asm volatile("ldmatrix.sync.aligned.m8n8.x4.shared.b16 {%0,%1,%2,%3}, [%4];\n" \
                 : "=r"(r0), "=r"(r1), "=r"(r2), "=r"(r3) : "r"(addr))

#define MMA16816(d0, d1, d2, d3, a0, a1, a2, a3, b0, b1) \
    asm volatile("mma.sync.aligned.m16n8k16.row.col.f32.bf16.bf16.f32 " \
                 "{%0,%1,%2,%3}, {%4,%5,%6,%7}, {%8,%9}, {%0,%1,%2,%3};\n" \
                 : "+f"(d0), "+f"(d1), "+f"(d2), "+f"(d3) \
                 : "r"(a0), "r"(a1), "r"(a2), "r"(a3), "r"(b0), "r"(b1))

// ---------------------------------------------------------------------------
// Kernel 1: L2-normalize rows -> bf16 scratch
// ---------------------------------------------------------------------------
__global__ void k_norm(const float* __restrict__ f, int N) {
    int row = blockIdx.x;
    __shared__ float red[8];
    const float* fr = f + (size_t)row * D;
    float ss = 0.f;
    for (int c = threadIdx.x; c < D; c += 256) { float v = fr[c]; ss += v * v; }
    for (int o = 16; o; o >>= 1) ss += __shfl_xor_sync(~0u, ss, o);
    if ((threadIdx.x & 31) == 0) red[threadIdx.x >> 5] = ss;
    __syncthreads();
    if (threadIdx.x < 32) {
        float v = (threadIdx.x < 8) ? red[threadIdx.x] : 0.f;
        for (int o = 4; o; o >>= 1) v += __shfl_xor_sync(~0u, v, o);
        if (threadIdx.x == 0) red[0] = v;
    }
    __syncthreads();
    float inv = 1.0f / fmaxf(sqrtf(red[0]), 1e-12f);
    __nv_bfloat16* out = g_fb + (size_t)row * D;
    for (int c = threadIdx.x; c < D; c += 256)
        out[c] = __float2bfloat16(fr[c] * inv);
}

// ---------------------------------------------------------------------------
// Kernel 2: fused S = f f^T tile GEMM + exp + masked reductions.
// SYMMETRY: only upper-triangular tiles (bi <= bj) are computed.
// Off-diagonal tiles emit BOTH row sums (rows of bi, slot bj) and
// column sums (== row sums of rows of bj over columns bi, slot bi).
// Deterministic: each (row, slot) pair written by exactly one block.
// ---------------------------------------------------------------------------
__global__ __launch_bounds__(256, 2)
void k_gemm(const int* __restrict__ labels, int N) {
    __shared__ __nv_bfloat16 sA[2][BM * LDSW];
    __shared__ __nv_bfloat16 sB[2][BN * LDSW];
    __shared__ int   lA[BM], lB[BN];
    __shared__ float wtot[8][64], wpos[8][64];
    __shared__ float ctot[8][32], cpos[8][32];

    const int bi = blockIdx.y;
    const int bj = blockIdx.x;
    if (bj < bi) return;                 // lower triangle: skip (symmetry)

    const int tid  = threadIdx.x;
    const int lane = tid & 31;
    const int wid  = tid >> 5;
    const int wm   = wid >> 2;   // 0..1  (64 rows each)
    const int wn   = wid & 3;    // 0..3  (32 cols each)
    const int bi0  = bi * BM;
    const int bj0  = bj * BN;

    if (tid < BM)       lA[tid]        = labels[bi0 + tid];
    else                lB[tid - BM]   = labels[bj0 + (tid - BM)];

    // global->shared copy geometry: each thread owns one row, two 16B chunks
    const int lrow  = tid >> 1;
    const int cbase = (tid & 1) * 16;   // element offset

#define LOAD_TILE(st, kt) do {                                                    \
        const __nv_bfloat16* ga = g_fb + (size_t)(bi0 + lrow) * D + (kt) * BK + cbase; \
        const __nv_bfloat16* gb = g_fb + (size_t)(bj0 + lrow) * D + (kt) * BK + cbase; \
        unsigned da = smem_u32(&sA[st][lrow * LDSW + cbase]);                     \
        unsigned db = smem_u32(&sB[st][lrow * LDSW + cbase]);                     \
        CPA(da, ga); CPA(da + 16, ga + 8);                                        \
        CPA(db, gb); CPA(db + 16, gb + 8);                                        \
        CPCOMMIT();                                                               \
    } while (0)

    float acc[4][4][4];
#pragma unroll
    for (int mt = 0; mt < 4; ++mt)
#pragma unroll
        for (int nt = 0; nt < 4; ++nt)
#pragma unroll
            for (int k = 0; k < 4; ++k) acc[mt][nt][k] = 0.f;

    const int KT = D / BK;  // 16
    LOAD_TILE(0, 0);

    for (int kt = 0; kt < KT; ++kt) {
        const int st = kt & 1;
        if (kt + 1 < KT) {
            LOAD_TILE((kt + 1) & 1, kt + 1);
            asm volatile("cp.async.wait_group 1;\n");
        } else {
            asm volatile("cp.async.wait_group 0;\n");
        }
        __syncthreads();

#pragma unroll
        for (int kc = 0; kc < 2; ++kc) {          // two k16 chunks per BK=32
            unsigned a[4][4], b[4][2];
#pragma unroll
            for (int mt = 0; mt < 4; ++mt) {
                int arow = wm * 64 + mt * 16 + (lane & 15);
                int acol = kc * 16 + ((lane >> 4) << 3);
                LDSM4(a[mt][0], a[mt][1], a[mt][2], a[mt][3],
                      smem_u32(&sA[st][arow * LDSW + acol]));
            }
#pragma unroll
            for (int p = 0; p < 2; ++p) {
                int brow = wn * 32 + p * 16 + ((lane >> 4) << 3) + (lane & 7);
                int bcol = kc * 16 + (((lane >> 3) & 1) << 3);
                LDSM4(b[2 * p][0], b[2 * p][1], b[2 * p + 1][0], b[2 * p + 1][1],
                      smem_u32(&sB[st][brow * LDSW + bcol]));
            }
#pragma unroll
            for (int mt = 0; mt < 4; ++mt)
#pragma unroll
                for (int nt = 0; nt < 4; ++nt)
                    MMA16816(acc[mt][nt][0], acc[mt][nt][1], acc[mt][nt][2], acc[mt][nt][3],
                             a[mt][0], a[mt][1], a[mt][2], a[mt][3],
                             b[nt][0], b[nt][1]);
        }
        __syncthreads();
    }

    // ---- epilogue ----
    // labels for this thread's fragment rows/cols
    int lai[4][2], lbj[4][2];
#pragma unroll
    for (int mt = 0; mt < 4; ++mt)
#pragma unroll
        for (int r = 0; r < 2; ++r)
            lai[mt][r] = lA[wm * 64 + mt * 16 + (lane >> 2) + r * 8];
#pragma unroll
    for (int nt = 0; nt < 4; ++nt)
#pragma unroll
        for (int c = 0; c < 2; ++c)
            lbj[nt][c] = lB[wn * 32 + nt * 8 + (lane & 3) * 2 + c];

    // in-place: acc <- exp2(s * SC), zeroed on the true diagonal
    const float SC = 20.60992915555662f;   // 1 / (0.07 * ln 2)
#pragma unroll
    for (int mt = 0; mt < 4; ++mt)
#pragma unroll
        for (int nt = 0; nt < 4; ++nt)
#pragma unroll
            for (int r = 0; r < 2; ++r)
#pragma unroll
                for (int c = 0; c < 2; ++c) {
                    const int gi = bi0 + wm * 64 + mt * 16 + (lane >> 2) + r * 8;
                    const int gj = bj0 + wn * 32 + nt * 8 + (lane & 3) * 2 + c;
                    float e = exp2f(acc[mt][nt][r * 2 + c] * SC);
                    acc[mt][nt][r * 2 + c] = (gi == gj) ? 0.f : e;
                }

    // column sums (for the mirrored rows of block bj), accumulated alongside
    float ct[4][2] = {}, cp[4][2] = {};

    // row sums
#pragma unroll
    for (int mt = 0; mt < 4; ++mt) {
#pragma unroll
        for (int r = 0; r < 2; ++r) {
            float t = 0.f, pq = 0.f;
            const int la = lai[mt][r];
#pragma unroll
            for (int nt = 0; nt < 4; ++nt) {
#pragma unroll
                for (int c = 0; c < 2; ++c) {
                    float e = acc[mt][nt][r * 2 + c];
                    t += e;
                    bool eq = (la == lbj[nt][c]);
                    if (eq) pq += e;
                    ct[nt][c] += e;
                    if (eq) cp[nt][c] += e;
                }
            }
            t  += __shfl_xor_sync(~0u, t, 1);  t  += __shfl_xor_sync(~0u, t, 2);
            pq += __shfl_xor_sync(~0u, pq, 1); pq += __shfl_xor_sync(~0u, pq, 2);
            if ((lane & 3) == 0) {
                int wr = mt * 16 + r * 8 + (lane >> 2);  // row within warp's 64
                wtot[wid][wr] = t;
                wpos[wid][wr] = pq;
            }
        }
    }

    // reduce column sums over the 8 row-groups within the warp
#pragma unroll
    for (int nt = 0; nt < 4; ++nt)
#pragma unroll
        for (int c = 0; c < 2; ++c) {
            float t = ct[nt][c], p = cp[nt][c];
            t += __shfl_xor_sync(~0u, t, 4);  p += __shfl_xor_sync(~0u, p, 4);
            t += __shfl_xor_sync(~0u, t, 8);  p += __shfl_xor_sync(~0u, p, 8);
            t += __shfl_xor_sync(~0u, t, 16); p += __shfl_xor_sync(~0u, p, 16);
            ct[nt][c] = t; cp[nt][c] = p;
        }
    if (lane < 4) {
#pragma unroll
        for (int nt = 0; nt < 4; ++nt)
#pragma unroll
            for (int c = 0; c < 2; ++c) {
                int col = nt * 8 + lane * 2 + c;
                ctot[wid][col] = ct[nt][c];
                cpos[wid][col] = cp[nt][c];
            }
    }
    __syncthreads();

    if (tid < BM) {
        // row partials: combine 4 warp_n slices, write slot bj
        const int wmm = tid >> 6;
        const int wr  = tid & 63;
        float t = 0.f, p = 0.f;
#pragma unroll
        for (int w = 0; w < 4; ++w) {
            t += wtot[wmm * 4 + w][wr];
            p += wpos[wmm * 4 + w][wr];
        }
        const int gi = bi0 + wmm * 64 + wr;
        g_ptot[(size_t)gi * NBLK + bj] = t;
        g_ppos[(size_t)gi * NBLK + bj] = p;
    } else if (bi != bj) {
        // column partials: combine 2 warp_m slices, write slot bi (mirrored rows)
        const int j = tid - BM;           // 0..127
        const int w = j >> 5;             // wn
        const int cc = j & 31;
        float t = ctot[w][cc] + ctot[4 + w][cc];
        float p = cpos[w][cc] + cpos[4 + w][cc];
        const int gj = bj0 + j;
        g_ptot[(size_t)gj * NBLK + bi] = t;
        g_ppos[(size_t)gj * NBLK + bi] = p;
    }
#undef LOAD_TILE
}

// ---------------------------------------------------------------------------
// Kernel 3: per-row combine + log, block partial sums (double)
// ---------------------------------------------------------------------------
__global__ void k_row(int N) {
    const int row = blockIdx.x * 128 + threadIdx.x;
    float t = 0.f, p = 0.f;
    const float* pt = g_ptot + (size_t)row * NBLK;
    const float* pp = g_ppos + (size_t)row * NBLK;
#pragma unroll 8
    for (int k = 0; k < NBLK; ++k) { t += pt[k]; p += pp[k]; }
    float ratio = (p + 1e-7f * t) / t;
    __shared__ double sred[128];
    sred[threadIdx.x] = (double)logf(ratio);
    __syncthreads();
    for (int s = 64; s; s >>= 1) {
        if (threadIdx.x < s) sred[threadIdx.x] += sred[threadIdx.x + s];
        __syncthreads();
    }
    if (threadIdx.x == 0) g_bsum[blockIdx.x] = sred[0];
}

// ---------------------------------------------------------------------------
// Kernel 4: final reduction, mean, negate, finiteness guard
// ---------------------------------------------------------------------------
__global__ void k_final(float* __restrict__ out, int N) {
    __shared__ double sred[64];
    sred[threadIdx.x] = g_bsum[threadIdx.x];
    __syncthreads();
    for (int s = 32; s; s >>= 1) {
        if (threadIdx.x < s) sred[threadIdx.x] += sred[threadIdx.x + s];
        __syncthreads();
    }
    if (threadIdx.x == 0) {
        float L = (float)(-sred[0] / (double)N);
        if (!isfinite(L)) L = 0.f;
        out[0] = L;
    }
}

extern "C" void kernel_launch(void* const* d_in, const int* in_sizes, int n_in,
                              void* d_out, int out_size) {
    const float* f  = (const float*)d_in[0];
    const int*   lb = (const int*)d_in[1];   // jax int64 request downcasts to int32 (x64 off)
    int N = in_sizes[1];                     // 8192

    k_norm<<<N, 256>>>(f, N);
    dim3 grid(N / BN, N / BM);
    k_gemm<<<grid, 256>>>(lb, N);
    k_row<<<N / 128, 128>>>(N);
    k_final<<<1, 64>>>((float*)d_out, N);
}

// round 3
// speedup vs baseline: 1.7089x; 1.0003x over previous
#include <cuda_runtime.h>
#include <cuda_bf16.h>
#include <math.h>

#define D   512
#define MAXN 8192
#define BM  128
#define BN  128
#define BK  32
#define LDSW 40            // smem row stride in bf16 elems (pad 32->40: conflict-free ldmatrix)
#define NBLK (MAXN / BN)   // 64 column-blocks

// scratch (no cudaMalloc allowed)
__device__ __nv_bfloat16 g_fb[MAXN * D];
__device__ float  g_ptot[(size_t)MAXN * NBLK];
__device__ float  g_ppos[(size_t)MAXN * NBLK];
__device__ double g_bsum[64];

__device__ __forceinline__ unsigned smem_u32(const void* p) {
    return (unsigned)__cvta_generic_to_shared(p);
}

#define CPA(dst, src) asm volatile("cp.async.cg.shared.global [%0], [%1], 16;\n" :: "r"(dst), "l"(src))
#define CPCOMMIT()    asm volatile("cp.async.commit_group;\n")

#define LDSM4(r0, r1, r2, r3, addr) \
    asm volatile("ldmatrix.sync.aligned.m8n8.x4.shared.b16 {%0,%1,%2,%3}, [%4];\n" \
                 : "=r"(r0), "=r"(r1), "=r"(r2), "=r"(r3) : "r"(addr))

#define MMA16816(d0, d1, d2, d3, a0, a1, a2, a3, b0, b1) \
    asm volatile("mma.sync.aligned.m16n8k16.row.col.f32.bf16.bf16.f32 " \
                 "{%0,%1,%2,%3}, {%4,%5,%6,%7}, {%8,%9}, {%0,%1,%2,%3};\n" \
                 : "+f"(d0), "+f"(d1), "+f"(d2), "+f"(d3) \
                 : "r"(a0), "r"(a1), "r"(a2), "r"(a3), "r"(b0), "r"(b1))

// ---------------------------------------------------------------------------
// Kernel 1: L2-normalize rows -> bf16 scratch
// ---------------------------------------------------------------------------
__global__ void k_norm(const float* __restrict__ f, int N) {
    int row = blockIdx.x;
    __shared__ float red[8];
    const float* fr = f + (size_t)row * D;
    float ss = 0.f;
    for (int c = threadIdx.x; c < D; c += 256) { float v = fr[c]; ss += v * v; }
    for (int o = 16; o; o >>= 1) ss += __shfl_xor_sync(~0u, ss, o);
    if ((threadIdx.x & 31) == 0) red[threadIdx.x >> 5] = ss;
    __syncthreads();
    if (threadIdx.x < 32) {
        float v = (threadIdx.x < 8) ? red[threadIdx.x] : 0.f;
        for (int o = 4; o; o >>= 1) v += __shfl_xor_sync(~0u, v, o);
        if (threadIdx.x == 0) red[0] = v;
    }
    __syncthreads();
    float inv = 1.0f / fmaxf(sqrtf(red[0]), 1e-12f);
    __nv_bfloat16* out = g_fb + (size_t)row * D;
    for (int c = threadIdx.x; c < D; c += 256)
        out[c] = __float2bfloat16(fr[c] * inv);
}

// ---------------------------------------------------------------------------
// Kernel 2: fused S = f f^T tile GEMM + exp + masked reductions.
// SYMMETRY: only upper-triangular tiles (bi <= bj) are computed.
// Off-diagonal tiles emit BOTH row sums (rows of bi, slot bj) and
// column sums (== row sums of rows of bj over columns bi, slot bi).
// Deterministic: each (row, slot) pair written by exactly one block.
// ---------------------------------------------------------------------------
__global__ __launch_bounds__(256, 2)
void k_gemm(const int* __restrict__ labels, int N) {
    __shared__ __nv_bfloat16 sA[2][BM * LDSW];
    __shared__ __nv_bfloat16 sB[2][BN * LDSW];
    __shared__ int   lA[BM], lB[BN];
    __shared__ float wtot[8][64], wpos[8][64];
    __shared__ float ctot[8][32], cpos[8][32];

    const int bi = blockIdx.y;
    const int bj = blockIdx.x;
    if (bj < bi) return;                 // lower triangle: skip (symmetry)

    const int tid  = threadIdx.x;
    const int lane = tid & 31;
    const int wid  = tid >> 5;
    const int wm   = wid >> 2;   // 0..1  (64 rows each)
    const int wn   = wid & 3;    // 0..3  (32 cols each)
    const int bi0  = bi * BM;
    const int bj0  = bj * BN;

    if (tid < BM)       lA[tid]        = labels[bi0 + tid];
    else                lB[tid - BM]   = labels[bj0 + (tid - BM)];

    // global->shared copy geometry: each thread owns one row, two 16B chunks
    const int lrow  = tid >> 1;
    const int cbase = (tid & 1) * 16;   // element offset

#define LOAD_TILE(st, kt) do {                                                    \
        const __nv_bfloat16* ga = g_fb + (size_t)(bi0 + lrow) * D + (kt) * BK + cbase; \
        const __nv_bfloat16* gb = g_fb + (size_t)(bj0 + lrow) * D + (kt) * BK + cbase; \
        unsigned da = smem_u32(&sA[st][lrow * LDSW + cbase]);                     \
        unsigned db = smem_u32(&sB[st][lrow * LDSW + cbase]);                     \
        CPA(da, ga); CPA(da + 16, ga + 8);                                        \
        CPA(db, gb); CPA(db + 16, gb + 8);                                        \
        CPCOMMIT();                                                               \
    } while (0)

    float acc[4][4][4];
#pragma unroll
    for (int mt = 0; mt < 4; ++mt)
#pragma unroll
        for (int nt = 0; nt < 4; ++nt)
#pragma unroll
            for (int k = 0; k < 4; ++k) acc[mt][nt][k] = 0.f;

    const int KT = D / BK;  // 16
    LOAD_TILE(0, 0);

    for (int kt = 0; kt < KT; ++kt) {
        const int st = kt & 1;
        if (kt + 1 < KT) {
            LOAD_TILE((kt + 1) & 1, kt + 1);
            asm volatile("cp.async.wait_group 1;\n");
        } else {
            asm volatile("cp.async.wait_group 0;\n");
        }
        __syncthreads();

#pragma unroll
        for (int kc = 0; kc < 2; ++kc) {          // two k16 chunks per BK=32
            unsigned a[4][4], b[4][2];
#pragma unroll
            for (int mt = 0; mt < 4; ++mt) {
                int arow = wm * 64 + mt * 16 + (lane & 15);
                int acol = kc * 16 + ((lane >> 4) << 3);
                LDSM4(a[mt][0], a[mt][1], a[mt][2], a[mt][3],
                      smem_u32(&sA[st][arow * LDSW + acol]));
            }
#pragma unroll
            for (int p = 0; p < 2; ++p) {
                int brow = wn * 32 + p * 16 + ((lane >> 4) << 3) + (lane & 7);
                int bcol = kc * 16 + (((lane >> 3) & 1) << 3);
                LDSM4(b[2 * p][0], b[2 * p][1], b[2 * p + 1][0], b[2 * p + 1][1],
                      smem_u32(&sB[st][brow * LDSW + bcol]));
            }
#pragma unroll
            for (int mt = 0; mt < 4; ++mt)
#pragma unroll
                for (int nt = 0; nt < 4; ++nt)
                    MMA16816(acc[mt][nt][0], acc[mt][nt][1], acc[mt][nt][2], acc[mt][nt][3],
                             a[mt][0], a[mt][1], a[mt][2], a[mt][3],
                             b[nt][0], b[nt][1]);
        }
        __syncthreads();
    }

    // ---- epilogue ----
    // labels for this thread's fragment rows/cols
    int lai[4][2], lbj[4][2];
#pragma unroll
    for (int mt = 0; mt < 4; ++mt)
#pragma unroll
        for (int r = 0; r < 2; ++r)
            lai[mt][r] = lA[wm * 64 + mt * 16 + (lane >> 2) + r * 8];
#pragma unroll
    for (int nt = 0; nt < 4; ++nt)
#pragma unroll
        for (int c = 0; c < 2; ++c)
            lbj[nt][c] = lB[wn * 32 + nt * 8 + (lane & 3) * 2 + c];

    // in-place: acc <- exp2(s * SC), zeroed on the true diagonal
    const float SC = 20.60992915555662f;   // 1 / (0.07 * ln 2)
#pragma unroll
    for (int mt = 0; mt < 4; ++mt)
#pragma unroll
        for (int nt = 0; nt < 4; ++nt)
#pragma unroll
            for (int r = 0; r < 2; ++r)
#pragma unroll
                for (int c = 0; c < 2; ++c) {
                    const int gi = bi0 + wm * 64 + mt * 16 + (lane >> 2) + r * 8;
                    const int gj = bj0 + wn * 32 + nt * 8 + (lane & 3) * 2 + c;
                    float e = exp2f(acc[mt][nt][r * 2 + c] * SC);
                    acc[mt][nt][r * 2 + c] = (gi == gj) ? 0.f : e;
                }

    // column sums (for the mirrored rows of block bj), accumulated alongside
    float ct[4][2] = {}, cp[4][2] = {};

    // row sums
#pragma unroll
    for (int mt = 0; mt < 4; ++mt) {
#pragma unroll
        for (int r = 0; r < 2; ++r) {
            float t = 0.f, pq = 0.f;
            const int la = lai[mt][r];
#pragma unroll
            for (int nt = 0; nt < 4; ++nt) {
#pragma unroll
                for (int c = 0; c < 2; ++c) {
                    float e = acc[mt][nt][r * 2 + c];
                    t += e;
                    bool eq = (la == lbj[nt][c]);
                    if (eq) pq += e;
                    ct[nt][c] += e;
                    if (eq) cp[nt][c] += e;
                }
            }
            t  += __shfl_xor_sync(~0u, t, 1);  t  += __shfl_xor_sync(~0u, t, 2);
            pq += __shfl_xor_sync(~0u, pq, 1); pq += __shfl_xor_sync(~0u, pq, 2);
            if ((lane & 3) == 0) {
                int wr = mt * 16 + r * 8 + (lane >> 2);  // row within warp's 64
                wtot[wid][wr] = t;
                wpos[wid][wr] = pq;
            }
        }
    }

    // reduce column sums over the 8 row-groups within the warp
#pragma unroll
    for (int nt = 0; nt < 4; ++nt)
#pragma unroll
        for (int c = 0; c < 2; ++c) {
            float t = ct[nt][c], p = cp[nt][c];
            t += __shfl_xor_sync(~0u, t, 4);  p += __shfl_xor_sync(~0u, p, 4);
            t += __shfl_xor_sync(~0u, t, 8);  p += __shfl_xor_sync(~0u, p, 8);
            t += __shfl_xor_sync(~0u, t, 16); p += __shfl_xor_sync(~0u, p, 16);
            ct[nt][c] = t; cp[nt][c] = p;
        }
    if (lane < 4) {
#pragma unroll
        for (int nt = 0; nt < 4; ++nt)
#pragma unroll
            for (int c = 0; c < 2; ++c) {
                int col = nt * 8 + lane * 2 + c;
                ctot[wid][col] = ct[nt][c];
                cpos[wid][col] = cp[nt][c];
            }
    }
    __syncthreads();

    if (tid < BM) {
        // row partials: combine 4 warp_n slices, write slot bj
        const int wmm = tid >> 6;
        const int wr  = tid & 63;
        float t = 0.f, p = 0.f;
#pragma unroll
        for (int w = 0; w < 4; ++w) {
            t += wtot[wmm * 4 + w][wr];
            p += wpos[wmm * 4 + w][wr];
        }
        const int gi = bi0 + wmm * 64 + wr;
        g_ptot[(size_t)gi * NBLK + bj] = t;
        g_ppos[(size_t)gi * NBLK + bj] = p;
    } else if (bi != bj) {
        // column partials: combine 2 warp_m slices, write slot bi (mirrored rows)
        const int j = tid - BM;           // 0..127
        const int w = j >> 5;             // wn
        const int cc = j & 31;
        float t = ctot[w][cc] + ctot[4 + w][cc];
        float p = cpos[w][cc] + cpos[4 + w][cc];
        const int gj = bj0 + j;
        g_ptot[(size_t)gj * NBLK + bi] = t;
        g_ppos[(size_t)gj * NBLK + bi] = p;
    }
#undef LOAD_TILE
}

// ---------------------------------------------------------------------------
// Kernel 3: per-row combine + log, block partial sums (double)
// ---------------------------------------------------------------------------
__global__ void k_row(int N) {
    const int row = blockIdx.x * 128 + threadIdx.x;
    float t = 0.f, p = 0.f;
    const float* pt = g_ptot + (size_t)row * NBLK;
    const float* pp = g_ppos + (size_t)row * NBLK;
#pragma unroll 8
    for (int k = 0; k < NBLK; ++k) { t += pt[k]; p += pp[k]; }
    float ratio = (p + 1e-7f * t) / t;
    __shared__ double sred[128];
    sred[threadIdx.x] = (double)logf(ratio);
    __syncthreads();
    for (int s = 64; s; s >>= 1) {
        if (threadIdx.x < s) sred[threadIdx.x] += sred[threadIdx.x + s];
        __syncthreads();
    }
    if (threadIdx.x == 0) g_bsum[blockIdx.x] = sred[0];
}

// ---------------------------------------------------------------------------
// Kernel 4: final reduction, mean, negate, finiteness guard
// ---------------------------------------------------------------------------
__global__ void k_final(float* __restrict__ out, int N) {
    __shared__ double sred[64];
    sred[threadIdx.x] = g_bsum[threadIdx.x];
    __syncthreads();
    for (int s = 32; s; s >>= 1) {
        if (threadIdx.x < s) sred[threadIdx.x] += sred[threadIdx.x + s];
        __syncthreads();
    }
    if (threadIdx.x == 0) {
        float L = (float)(-sred[0] / (double)N);
        if (!isfinite(L)) L = 0.f;
        out[0] = L;
    }
}

extern "C" void kernel_launch(void* const* d_in, const int* in_sizes, int n_in,
                              void* d_out, int out_size) {
    const float* f  = (const float*)d_in[0];
    const int*   lb = (const int*)d_in[1];   // jax int64 request downcasts to int32 (x64 off)
    int N = in_sizes[1];                     // 8192

    k_norm<<<N, 256>>>(f, N);
    dim3 grid(N / BN, N / BM);
    k_gemm<<<grid, 256>>>(lb, N);
    k_row<<<N / 128, 128>>>(N);
    k_final<<<1, 64>>>((float*)d_out, N);
}